// round 1
// baseline (speedup 1.0000x reference)
#include <cuda_runtime.h>
#include <math.h>

// ---------------------------------------------------------------------------
// MHCN encoder on GB300. All scratch in one static __device__ buffer.
// ---------------------------------------------------------------------------

#define NU 100000
#define NI 50000
#define DD 64
#define EPSV 1e-12f

typedef long long ll;

static constexpr ll S  = (ll)NU * DD;   // 6,400,000
static constexpr ll SI = (ll)NI * DD;   // 3,200,000

// g_buf offsets (floats)
static constexpr ll UC0 = 0;
static constexpr ll UC1 = 1 * S;
static constexpr ll UC2 = 2 * S;
static constexpr ll ACC0 = 3 * S;
static constexpr ll ACC1 = 4 * S;
static constexpr ll ACC2 = 5 * S;
static constexpr ll TMP0 = 6 * S;
static constexpr ll TMP1 = 7 * S;
static constexpr ll TMP2 = 8 * S;
static constexpr ll USTMP = 9 * S;
static constexpr ll USIMPLE = 10 * S;
static constexpr ll ACCS = 11 * S;
static constexpr ll MIXED = 12 * S;
static constexpr ll ITEMA = 13 * S;
static constexpr ll ITEMB = 13 * S + SI;
static constexpr ll VOFF  = 13 * S + 2 * SI;
static constexpr ll TOTAL = VOFF + 64;

__device__ float g_buf[TOTAL];

// ---------------------------------------------------------------------------
// helpers
// ---------------------------------------------------------------------------
__device__ __forceinline__ float warp_sum(float v) {
#pragma unroll
    for (int o = 16; o > 0; o >>= 1) v += __shfl_xor_sync(0xFFFFFFFFu, v, o);
    return v;
}

__device__ __forceinline__ void red_add_v4(float* p, float a, float b, float c, float d) {
    asm volatile("red.global.add.v4.f32 [%0], {%1, %2, %3, %4};"
                 :: "l"(p), "f"(a), "f"(b), "f"(c), "f"(d) : "memory");
}

// ---------------------------------------------------------------------------
// kernels
// ---------------------------------------------------------------------------
__global__ void zero_kernel(ll off, ll n4) {
    ll i = (ll)blockIdx.x * blockDim.x + threadIdx.x;
    if (i < n4) ((float4*)(g_buf + off))[i] = make_float4(0.f, 0.f, 0.f, 0.f);
}

// v[d] = sum_j att_mat[d][j] * att_agg[j]
__global__ void compute_v_kernel(const float* __restrict__ att_mat,
                                 const float* __restrict__ att_agg) {
    int d = threadIdx.x;
    float s = 0.f;
#pragma unroll
    for (int j = 0; j < DD; ++j) s = fmaf(att_mat[d * DD + j], att_agg[j], s);
    g_buf[VOFF + d] = s;
}

// COO SpMM: y[row[e], :] += val[e] * x[col[e], :]. 16 threads per edge (float4).
__global__ void spmm_kernel(const int* __restrict__ row, const int* __restrict__ col,
                            const float* __restrict__ val, int nnz,
                            const float* __restrict__ x_ext, ll x_off, ll y_off) {
    ll t = (ll)blockIdx.x * blockDim.x + threadIdx.x;
    int e = (int)(t >> 4);
    if (e >= nnz) return;
    int j = (int)(t & 15);
    int r = __ldg(row + e);
    int c = __ldg(col + e);
    float v = __ldg(val + e);
    const float* x = x_ext ? x_ext : (const float*)g_buf + x_off;
    float4 xv = *(const float4*)(x + (ll)c * DD + j * 4);
    red_add_v4(g_buf + y_off + (ll)r * DD + j * 4,
               v * xv.x, v * xv.y, v * xv.z, v * xv.w);
}

// acc[r,:] += x[r,:] / max(||x[r,:]||, eps). One warp per row.
__global__ void l2acc_kernel(ll x_off, float* acc_ext, ll acc_off, int n_rows) {
    int w = (int)(((ll)blockIdx.x * blockDim.x + threadIdx.x) >> 5);
    int lane = threadIdx.x & 31;
    if (w >= n_rows) return;
    ll base = (ll)w * DD + lane * 2;
    float2 x = *(const float2*)(g_buf + x_off + base);
    float ss = warp_sum(x.x * x.x + x.y * x.y);
    float scale = 1.f / fmaxf(sqrtf(ss), EPSV);
    float* acc = (acc_ext ? acc_ext : (float*)g_buf) + acc_off + base;
    float2 a = *(const float2*)acc;
    a.x += x.x * scale;
    a.y += x.y * scale;
    *(float2*)acc = a;
}

// channel attention: out = sa * softmax-mix(c0,c1,c2) + sb * other. One warp per row.
__global__ void attn_kernel(ll c0o, ll c1o, ll c2o, ll otho,
                            float sa, float sb,
                            float* out_ext, ll out_off, int n_rows) {
    int w = (int)(((ll)blockIdx.x * blockDim.x + threadIdx.x) >> 5);
    int lane = threadIdx.x & 31;
    if (w >= n_rows) return;
    ll base = (ll)w * DD + lane * 2;
    float2 c0 = *(const float2*)(g_buf + c0o + base);
    float2 c1 = *(const float2*)(g_buf + c1o + base);
    float2 c2 = *(const float2*)(g_buf + c2o + base);
    float2 ot = *(const float2*)(g_buf + otho + base);
    float2 vv = *(const float2*)(g_buf + VOFF + lane * 2);
    float w0 = warp_sum(c0.x * vv.x + c0.y * vv.y);
    float w1 = warp_sum(c1.x * vv.x + c1.y * vv.y);
    float w2 = warp_sum(c2.x * vv.x + c2.y * vv.y);
    float m = fmaxf(w0, fmaxf(w1, w2));
    float e0 = expf(w0 - m), e1 = expf(w1 - m), e2 = expf(w2 - m);
    float inv = 1.f / (e0 + e1 + e2);
    float s0 = e0 * inv, s1 = e1 * inv, s2 = e2 * inv;
    float ox = sa * (s0 * c0.x + s1 * c1.x + s2 * c2.x) + sb * ot.x;
    float oy = sa * (s0 * c0.y + s1 * c1.y + s2 * c2.y) + sb * ot.y;
    float* out = (out_ext ? out_ext : (float*)g_buf) + out_off + base;
    *(float2*)out = make_float2(ox, oy);
}

// self-gating: out_g = in * sigmoid(in @ W_g + b_g) for g in [0, n_gates).
// blockDim = (64, 4); each block handles a 32-row tile; W staged gate-by-gate.
__global__ void gating_kernel(const float* __restrict__ in, const float* __restrict__ W,
                              const float* __restrict__ Bb, int n_rows, int n_gates,
                              float* out_ext, ll o0, ll o1, ll o2, ll o3,
                              int dup_acc, ll a0, ll a1, ll a2, ll a3) {
    __shared__ float sW[DD * DD];
    __shared__ float se[32 * DD];
    int tx = threadIdx.x;           // 0..63 (output col)
    int ty = threadIdx.y;           // 0..3
    int tid = ty * 64 + tx;
    int row0 = blockIdx.x * 32;

    for (int i = tid; i < 32 * DD; i += 256) {
        int r = i / DD, c = i % DD;
        int gr = row0 + r;
        se[i] = (gr < n_rows) ? in[(ll)gr * DD + c] : 0.f;
    }

    ll outs[4] = {o0, o1, o2, o3};
    ll accs[4] = {a0, a1, a2, a3};

    for (int g = 0; g < n_gates; ++g) {
        __syncthreads();
        for (int i = tid; i < DD * DD; i += 256) sW[i] = W[(ll)g * DD * DD + i];
        __syncthreads();
        float bg = Bb[g * DD + tx];
        for (int r = ty; r < 32; r += 4) {
            int gr = row0 + r;
            if (gr >= n_rows) break;
            float acc = 0.f;
#pragma unroll
            for (int d = 0; d < DD; ++d) acc = fmaf(se[r * DD + d], sW[d * DD + tx], acc);
            float z = acc + bg;
            float sig = 1.f / (1.f + expf(-z));
            float o = se[r * DD + tx] * sig;
            ll idx = (ll)gr * DD + tx;
            float* outp = (out_ext ? out_ext : (float*)g_buf) + outs[g];
            outp[idx] = o;
            if (dup_acc) g_buf[accs[g] + idx] = o;
        }
    }
}

// ---------------------------------------------------------------------------
// host
// ---------------------------------------------------------------------------
static inline int blocks_for(ll threads, int bs) { return (int)((threads + bs - 1) / bs); }

extern "C" void kernel_launch(void* const* d_in, const int* in_sizes, int n_in,
                              void* d_out, int out_size) {
    const float* user_emb  = (const float*)d_in[0];
    const float* item_emb  = (const float*)d_in[1];
    const float* gating_w  = (const float*)d_in[2];
    const float* gating_b  = (const float*)d_in[3];
    const float* sgating_w = (const float*)d_in[4];
    const float* sgating_b = (const float*)d_in[5];
    const float* att_mat   = (const float*)d_in[6];
    const float* att_agg   = (const float*)d_in[7];
    const int*   hs_row = (const int*)d_in[8];
    const int*   hs_col = (const int*)d_in[9];
    const float* hs_val = (const float*)d_in[10];
    const int*   hj_row = (const int*)d_in[11];
    const int*   hj_col = (const int*)d_in[12];
    const float* hj_val = (const float*)d_in[13];
    const int*   hp_row = (const int*)d_in[14];
    const int*   hp_col = (const int*)d_in[15];
    const float* hp_val = (const float*)d_in[16];
    const int*   inter_row = (const int*)d_in[17];
    const int*   inter_col = (const int*)d_in[18];
    const float* inter_val = (const float*)d_in[19];

    const int NNZ_H = in_sizes[8];    // 3,200,000
    const int NNZ_I = in_sizes[17];   // 3,000,000

    float* out = (float*)d_out;
    // d_out layout: final_user [0,S), acc_item [S, S+SI), sg0/sg1/sg2 each S after.
    const ll O_FINAL = 0;
    const ll O_ITEM  = S;
    const ll O_SG0   = S + SI;
    const ll O_SG1   = 2 * S + SI;
    const ll O_SG2   = 3 * S + SI;

    const int ZBS = 256, WBS = 256, SBS = 256;
    dim3 gdim(64, 4);

    // v = att_mat @ att_agg^T
    compute_v_kernel<<<1, 64>>>(att_mat, att_agg);

    // 4 user gatings; duplicate into acc buffers (acc init = gated emb)
    gating_kernel<<<(NU + 31) / 32, gdim>>>(user_emb, gating_w, gating_b, NU, 4,
                                            nullptr, UC0, UC1, UC2, USIMPLE,
                                            1, ACC0, ACC1, ACC2, ACCS);

    // acc_item init = item_emb (into d_out)
    cudaMemcpyAsync(out + O_ITEM, item_emb, SI * sizeof(float),
                    cudaMemcpyDeviceToDevice, 0);

    const int uwb = blocks_for((ll)NU * 32, WBS);   // warp-per-row over users
    const int iwb = blocks_for((ll)NI * 32, WBS);   // warp-per-row over items
    const int sbH = blocks_for((ll)NNZ_H * 16, SBS);
    const int sbI = blocks_for((ll)NNZ_I * 16, SBS);

    // ---------------- layer 1 ----------------
    // targets: TMP0..2, USTMP (contiguous 6S..10S), ITEMA
    zero_kernel<<<blocks_for(4 * S / 4, ZBS), ZBS>>>(TMP0, 4 * S / 4);
    zero_kernel<<<blocks_for(SI / 4, ZBS), ZBS>>>(ITEMA, SI / 4);

    attn_kernel<<<uwb, WBS>>>(UC0, UC1, UC2, USIMPLE, 0.5f, 0.5f, nullptr, MIXED, NU);

    spmm_kernel<<<sbH, SBS>>>(hs_row, hs_col, hs_val, NNZ_H, nullptr, UC0, TMP0);
    spmm_kernel<<<sbH, SBS>>>(hj_row, hj_col, hj_val, NNZ_H, nullptr, UC1, TMP1);
    spmm_kernel<<<sbH, SBS>>>(hp_row, hp_col, hp_val, NNZ_H, nullptr, UC2, TMP2);
    // new_item = inter^T @ mixed : scatter to items
    spmm_kernel<<<sbI, SBS>>>(inter_col, inter_row, inter_val, NNZ_I, nullptr, MIXED, ITEMA);
    // u_simple = inter @ item_emb (old items)
    spmm_kernel<<<sbI, SBS>>>(inter_row, inter_col, inter_val, NNZ_I, item_emb, 0, USTMP);

    l2acc_kernel<<<uwb, WBS>>>(TMP0, nullptr, ACC0, NU);
    l2acc_kernel<<<uwb, WBS>>>(TMP1, nullptr, ACC1, NU);
    l2acc_kernel<<<uwb, WBS>>>(TMP2, nullptr, ACC2, NU);
    l2acc_kernel<<<iwb, WBS>>>(ITEMA, out, O_ITEM, NI);
    l2acc_kernel<<<uwb, WBS>>>(USTMP, nullptr, ACCS, NU);

    // ---------------- layer 2 ----------------
    // current: uc = TMP0..2, usimple = USTMP, it = ITEMA
    // targets: UC0..2 (0..3S), USIMPLE, ITEMB
    zero_kernel<<<blocks_for(3 * S / 4, ZBS), ZBS>>>(UC0, 3 * S / 4);
    zero_kernel<<<blocks_for(S / 4, ZBS), ZBS>>>(USIMPLE, S / 4);
    zero_kernel<<<blocks_for(SI / 4, ZBS), ZBS>>>(ITEMB, SI / 4);

    attn_kernel<<<uwb, WBS>>>(TMP0, TMP1, TMP2, USTMP, 0.5f, 0.5f, nullptr, MIXED, NU);

    spmm_kernel<<<sbH, SBS>>>(hs_row, hs_col, hs_val, NNZ_H, nullptr, TMP0, UC0);
    spmm_kernel<<<sbH, SBS>>>(hj_row, hj_col, hj_val, NNZ_H, nullptr, TMP1, UC1);
    spmm_kernel<<<sbH, SBS>>>(hp_row, hp_col, hp_val, NNZ_H, nullptr, TMP2, UC2);
    spmm_kernel<<<sbI, SBS>>>(inter_col, inter_row, inter_val, NNZ_I, nullptr, MIXED, ITEMB);
    spmm_kernel<<<sbI, SBS>>>(inter_row, inter_col, inter_val, NNZ_I, nullptr, ITEMA, USIMPLE);

    l2acc_kernel<<<uwb, WBS>>>(UC0, nullptr, ACC0, NU);
    l2acc_kernel<<<uwb, WBS>>>(UC1, nullptr, ACC1, NU);
    l2acc_kernel<<<uwb, WBS>>>(UC2, nullptr, ACC2, NU);
    l2acc_kernel<<<iwb, WBS>>>(ITEMB, out, O_ITEM, NI);
    l2acc_kernel<<<uwb, WBS>>>(USIMPLE, nullptr, ACCS, NU);

    // ---------------- final ----------------
    // final_user = attention(acc0,acc1,acc2) + acc_simple/2  -> d_out[0:S)
    attn_kernel<<<uwb, WBS>>>(ACC0, ACC1, ACC2, ACCS, 1.0f, 0.5f, out, O_FINAL, NU);

    // sg0..2 = self_gating(final_user, sgating) -> d_out
    gating_kernel<<<(NU + 31) / 32, gdim>>>(out + O_FINAL, sgating_w, sgating_b, NU, 3,
                                            out, O_SG0, O_SG1, O_SG2, 0,
                                            0, 0, 0, 0, 0);
}

// round 2
// speedup vs baseline: 1.6021x; 1.6021x over previous
#include <cuda_runtime.h>
#include <math.h>

#define NU 100000
#define NI 50000
#define DD 64
#define EPSV 1e-12f
#define MAXH 3200000
#define MAXI 3000000

typedef long long ll;

static constexpr ll S  = (ll)NU * DD;
static constexpr ll SI = (ll)NI * DD;

// dense scratch
static constexpr ll UC0 = 0;
static constexpr ll UC1 = 1 * S;
static constexpr ll UC2 = 2 * S;
static constexpr ll ACC0 = 3 * S;
static constexpr ll ACC1 = 4 * S;
static constexpr ll ACC2 = 5 * S;
static constexpr ll TMP0 = 6 * S;
static constexpr ll TMP1 = 7 * S;
static constexpr ll TMP2 = 8 * S;
static constexpr ll USTMP = 9 * S;
static constexpr ll USIMPLE = 10 * S;
static constexpr ll ACCS = 11 * S;
static constexpr ll MIXED = 12 * S;
static constexpr ll ITEMA = 13 * S;
static constexpr ll ITEMB = 13 * S + SI;
static constexpr ll VOFF  = 13 * S + 2 * SI;
static constexpr ll TOTAL = VOFF + 64;

__device__ float g_buf[TOTAL];

// CSR scratch: 5 regions (hs, hj, hp, inter-by-user, inter-by-item)
static constexpr int OFFLEN = 4 * (NU + 1) + (NI + 1);
__device__ int  g_off[OFFLEN];
__device__ int  g_cur[OFFLEN];             // counts during build, cursors during scatter
__device__ int2 g_pair[3 * (ll)MAXH + 2 * (ll)MAXI];

// ---------------------------------------------------------------------------
__device__ __forceinline__ float warp_sum(float v) {
#pragma unroll
    for (int o = 16; o > 0; o >>= 1) v += __shfl_xor_sync(0xFFFFFFFFu, v, o);
    return v;
}

// ---------------------------------------------------------------------------
__global__ void zero_int_kernel(int* p, int n) {
    int i = blockIdx.x * blockDim.x + threadIdx.x;
    if (i < n) p[i] = 0;
}

__global__ void hist_kernel(const int* __restrict__ row, int nnz, int* __restrict__ cnt) {
    int e = blockIdx.x * blockDim.x + threadIdx.x;
    if (e < nnz) atomicAdd(cnt + __ldg(row + e), 1);
}

// one block per region; exclusive scan of counts -> off and cur
__global__ void scan_kernel() {
    int region = blockIdx.x;
    int n = (region == 4) ? NI : NU;
    int base = region * (NU + 1);
    int* cnt = g_cur + base;
    int* off = g_off + base;
    int t = threadIdx.x;  // 1024
    __shared__ int wsum[32];
    __shared__ int s_carry;
    if (t == 0) s_carry = 0;
    __syncthreads();
    for (int b0 = 0; b0 < n; b0 += 1024) {
        int i = b0 + t;
        int v = (i < n) ? cnt[i] : 0;
        int x = v;
#pragma unroll
        for (int o = 1; o < 32; o <<= 1) {
            int y = __shfl_up_sync(0xFFFFFFFFu, x, o);
            if ((t & 31) >= o) x += y;
        }
        if ((t & 31) == 31) wsum[t >> 5] = x;
        __syncthreads();
        if (t < 32) {
            int y = wsum[t];
#pragma unroll
            for (int o = 1; o < 32; o <<= 1) {
                int z = __shfl_up_sync(0xFFFFFFFFu, y, o);
                if (t >= o) y += z;
            }
            wsum[t] = y;
        }
        __syncthreads();
        int incl = x + ((t >= 32) ? wsum[(t >> 5) - 1] : 0) + s_carry;
        if (i < n) { off[i] = incl - v; cnt[i] = incl - v; }
        __syncthreads();
        if (t == 1023) s_carry = incl;
        __syncthreads();
    }
    if (t == 0) off[n] = s_carry;
}

__global__ void scatter_kernel(const int* __restrict__ row, const int* __restrict__ col,
                               const float* __restrict__ val, int nnz,
                               int* __restrict__ cur, int2* __restrict__ pair) {
    int e = blockIdx.x * blockDim.x + threadIdx.x;
    if (e >= nnz) return;
    int r = __ldg(row + e);
    int pos = atomicAdd(cur + r, 1);
    pair[pos] = make_int2(__ldg(col + e), __float_as_int(__ldg(val + e)));
}

// CSR SpMM fused with l2norm-accumulate: one warp per row.
// y[r,:] = sum_e val * x[col,:];  acc[r,:] += y[r,:]/max(||y[r,:]||,eps)
__global__ void csr_spmm_kernel(const int* __restrict__ off, const int2* __restrict__ pair,
                                int n_rows, const float* __restrict__ x,
                                float* __restrict__ y, float* __restrict__ acc) {
    int w = (int)(((ll)blockIdx.x * blockDim.x + threadIdx.x) >> 5);
    if (w >= n_rows) return;
    int lane = threadIdx.x & 31;
    int s = __ldg(off + w), e = __ldg(off + w + 1);
    float ax = 0.f, ay = 0.f;
    int i = s;
    for (; i + 1 < e; i += 2) {
        int2 p0 = __ldg(pair + i);
        int2 p1 = __ldg(pair + i + 1);
        float2 x0 = *(const float2*)(x + (ll)p0.x * DD + lane * 2);
        float2 x1 = *(const float2*)(x + (ll)p1.x * DD + lane * 2);
        float v0 = __int_as_float(p0.y), v1 = __int_as_float(p1.y);
        ax = fmaf(v0, x0.x, ax); ay = fmaf(v0, x0.y, ay);
        ax = fmaf(v1, x1.x, ax); ay = fmaf(v1, x1.y, ay);
    }
    if (i < e) {
        int2 p0 = __ldg(pair + i);
        float2 x0 = *(const float2*)(x + (ll)p0.x * DD + lane * 2);
        float v0 = __int_as_float(p0.y);
        ax = fmaf(v0, x0.x, ax); ay = fmaf(v0, x0.y, ay);
    }
    ll base = (ll)w * DD + lane * 2;
    *(float2*)(y + base) = make_float2(ax, ay);
    float ss = warp_sum(ax * ax + ay * ay);
    float sc = 1.f / fmaxf(sqrtf(ss), EPSV);
    float2 a = *(const float2*)(acc + base);
    a.x = fmaf(ax, sc, a.x);
    a.y = fmaf(ay, sc, a.y);
    *(float2*)(acc + base) = a;
}

// v[d] = sum_j att_mat[d][j] * att_agg[j]
__global__ void compute_v_kernel(const float* __restrict__ att_mat,
                                 const float* __restrict__ att_agg) {
    int d = threadIdx.x;
    float s = 0.f;
#pragma unroll
    for (int j = 0; j < DD; ++j) s = fmaf(att_mat[d * DD + j], att_agg[j], s);
    g_buf[VOFF + d] = s;
}

// out = sa * softmax-mix(c0,c1,c2) + sb * oth.  one warp per row.
__global__ void attn_kernel(const float* __restrict__ c0p, const float* __restrict__ c1p,
                            const float* __restrict__ c2p, const float* __restrict__ othp,
                            const float* __restrict__ v, float sa, float sb,
                            float* __restrict__ out, int n_rows) {
    int w = (int)(((ll)blockIdx.x * blockDim.x + threadIdx.x) >> 5);
    if (w >= n_rows) return;
    int lane = threadIdx.x & 31;
    ll base = (ll)w * DD + lane * 2;
    float2 c0 = *(const float2*)(c0p + base);
    float2 c1 = *(const float2*)(c1p + base);
    float2 c2 = *(const float2*)(c2p + base);
    float2 ot = *(const float2*)(othp + base);
    float2 vv = *(const float2*)(v + lane * 2);
    float w0 = warp_sum(c0.x * vv.x + c0.y * vv.y);
    float w1 = warp_sum(c1.x * vv.x + c1.y * vv.y);
    float w2 = warp_sum(c2.x * vv.x + c2.y * vv.y);
    float m = fmaxf(w0, fmaxf(w1, w2));
    float e0 = __expf(w0 - m), e1 = __expf(w1 - m), e2 = __expf(w2 - m);
    float inv = 1.f / (e0 + e1 + e2);
    float s0 = e0 * inv, s1 = e1 * inv, s2 = e2 * inv;
    float ox = sa * (s0 * c0.x + s1 * c1.x + s2 * c2.x) + sb * ot.x;
    float oy = sa * (s0 * c0.y + s1 * c1.y + s2 * c2.y) + sb * ot.y;
    *(float2*)(out + base) = make_float2(ox, oy);
}

// self-gating: out_g = in * sigmoid(in @ W_g + b_g). blockDim (64,4), 32-row tile.
__global__ void gating_kernel(const float* __restrict__ in, const float* __restrict__ W,
                              const float* __restrict__ B, int n_rows, int n_gates,
                              float* o0, float* o1, float* o2, float* o3,
                              float* a0, float* a1, float* a2, float* a3) {
    __shared__ float sW[DD * DD];
    __shared__ float se[32 * DD];
    int tx = threadIdx.x, ty = threadIdx.y;
    int tid = ty * 64 + tx;
    int row0 = blockIdx.x * 32;
    for (int i = tid; i < 32 * DD; i += 256) {
        int r = i >> 6, c = i & 63;
        int gr = row0 + r;
        se[i] = (gr < n_rows) ? in[(ll)gr * DD + c] : 0.f;
    }
    float* outs[4] = {o0, o1, o2, o3};
    float* accs[4] = {a0, a1, a2, a3};
    for (int g = 0; g < n_gates; ++g) {
        __syncthreads();
        for (int i = tid; i < DD * DD; i += 256) sW[i] = W[(ll)g * DD * DD + i];
        __syncthreads();
        float bg = B[g * DD + tx];
        float acc[8] = {0, 0, 0, 0, 0, 0, 0, 0};
#pragma unroll 8
        for (int d = 0; d < DD; ++d) {
            float wv = sW[d * DD + tx];
#pragma unroll
            for (int rr = 0; rr < 8; ++rr)
                acc[rr] = fmaf(se[(ty + 4 * rr) * DD + d], wv, acc[rr]);
        }
#pragma unroll
        for (int rr = 0; rr < 8; ++rr) {
            int r = ty + 4 * rr;
            int gr = row0 + r;
            if (gr < n_rows) {
                float z = acc[rr] + bg;
                float sig = 1.f / (1.f + __expf(-z));
                float ov = se[r * DD + tx] * sig;
                ll idx = (ll)gr * DD + tx;
                outs[g][idx] = ov;
                if (a0) accs[g][idx] = ov;
            }
        }
    }
}

// ---------------------------------------------------------------------------
static inline int blocks_for(ll threads, int bs) { return (int)((threads + bs - 1) / bs); }

extern "C" void kernel_launch(void* const* d_in, const int* in_sizes, int n_in,
                              void* d_out, int out_size) {
    const float* user_emb  = (const float*)d_in[0];
    const float* item_emb  = (const float*)d_in[1];
    const float* gating_w  = (const float*)d_in[2];
    const float* gating_b  = (const float*)d_in[3];
    const float* sgating_w = (const float*)d_in[4];
    const float* sgating_b = (const float*)d_in[5];
    const float* att_mat   = (const float*)d_in[6];
    const float* att_agg   = (const float*)d_in[7];
    const int*   hs_row = (const int*)d_in[8];
    const int*   hs_col = (const int*)d_in[9];
    const float* hs_val = (const float*)d_in[10];
    const int*   hj_row = (const int*)d_in[11];
    const int*   hj_col = (const int*)d_in[12];
    const float* hj_val = (const float*)d_in[13];
    const int*   hp_row = (const int*)d_in[14];
    const int*   hp_col = (const int*)d_in[15];
    const float* hp_val = (const float*)d_in[16];
    const int*   inter_row = (const int*)d_in[17];
    const int*   inter_col = (const int*)d_in[18];
    const float* inter_val = (const float*)d_in[19];

    const int NNZ_H = in_sizes[8];
    const int NNZ_I = in_sizes[17];

    float* out = (float*)d_out;
    const ll O_ITEM = S;
    const ll O_SG0 = S + SI;
    const ll O_SG1 = 2 * S + SI;
    const ll O_SG2 = 3 * S + SI;

    float* gb;  cudaGetSymbolAddress((void**)&gb, g_buf);
    int*   off; cudaGetSymbolAddress((void**)&off, g_off);
    int*   cur; cudaGetSymbolAddress((void**)&cur, g_cur);
    int2*  pr;  cudaGetSymbolAddress((void**)&pr, g_pair);

    const int BS = 256;
    const int hbH = blocks_for(NNZ_H, BS);
    const int hbI = blocks_for(NNZ_I, BS);
    const int uwb = blocks_for((ll)NU * 32, BS);
    const int iwb = blocks_for((ll)NI * 32, BS);
    dim3 gdim(64, 4);

    // region bases
    int* c0 = cur + 0 * (NU + 1); int* f0 = off + 0 * (NU + 1); int2* p0 = pr;
    int* c1 = cur + 1 * (NU + 1); int* f1 = off + 1 * (NU + 1); int2* p1 = pr + (ll)NNZ_H;
    int* c2 = cur + 2 * (NU + 1); int* f2 = off + 2 * (NU + 1); int2* p2 = pr + 2ll * NNZ_H;
    int* c3 = cur + 3 * (NU + 1); int* f3 = off + 3 * (NU + 1); int2* p3 = pr + 3ll * NNZ_H;
    int* c4 = cur + 4 * (NU + 1); int* f4 = off + 4 * (NU + 1); int2* p4 = pr + 3ll * NNZ_H + NNZ_I;

    // ---- CSR build (5 matrices) ----
    zero_int_kernel<<<blocks_for(OFFLEN, BS), BS>>>(cur, OFFLEN);
    hist_kernel<<<hbH, BS>>>(hs_row, NNZ_H, c0);
    hist_kernel<<<hbH, BS>>>(hj_row, NNZ_H, c1);
    hist_kernel<<<hbH, BS>>>(hp_row, NNZ_H, c2);
    hist_kernel<<<hbI, BS>>>(inter_row, NNZ_I, c3);
    hist_kernel<<<hbI, BS>>>(inter_col, NNZ_I, c4);
    scan_kernel<<<5, 1024>>>();
    scatter_kernel<<<hbH, BS>>>(hs_row, hs_col, hs_val, NNZ_H, c0, p0);
    scatter_kernel<<<hbH, BS>>>(hj_row, hj_col, hj_val, NNZ_H, c1, p1);
    scatter_kernel<<<hbH, BS>>>(hp_row, hp_col, hp_val, NNZ_H, c2, p2);
    scatter_kernel<<<hbI, BS>>>(inter_row, inter_col, inter_val, NNZ_I, c3, p3);
    scatter_kernel<<<hbI, BS>>>(inter_col, inter_row, inter_val, NNZ_I, c4, p4);

    // ---- prologue ----
    compute_v_kernel<<<1, 64>>>(att_mat, att_agg);
    gating_kernel<<<(NU + 31) / 32, gdim>>>(user_emb, gating_w, gating_b, NU, 4,
                                            gb + UC0, gb + UC1, gb + UC2, gb + USIMPLE,
                                            gb + ACC0, gb + ACC1, gb + ACC2, gb + ACCS);
    cudaMemcpyAsync(out + O_ITEM, item_emb, SI * sizeof(float), cudaMemcpyDeviceToDevice, 0);

    // ---- layer 1 ----
    attn_kernel<<<uwb, BS>>>(gb + UC0, gb + UC1, gb + UC2, gb + USIMPLE, gb + VOFF,
                             0.5f, 0.5f, gb + MIXED, NU);
    csr_spmm_kernel<<<uwb, BS>>>(f0, p0, NU, gb + UC0, gb + TMP0, gb + ACC0);
    csr_spmm_kernel<<<uwb, BS>>>(f1, p1, NU, gb + UC1, gb + TMP1, gb + ACC1);
    csr_spmm_kernel<<<uwb, BS>>>(f2, p2, NU, gb + UC2, gb + TMP2, gb + ACC2);
    csr_spmm_kernel<<<iwb, BS>>>(f4, p4, NI, gb + MIXED, gb + ITEMA, out + O_ITEM);
    csr_spmm_kernel<<<uwb, BS>>>(f3, p3, NU, item_emb, gb + USTMP, gb + ACCS);

    // ---- layer 2 ----
    attn_kernel<<<uwb, BS>>>(gb + TMP0, gb + TMP1, gb + TMP2, gb + USTMP, gb + VOFF,
                             0.5f, 0.5f, gb + MIXED, NU);
    csr_spmm_kernel<<<uwb, BS>>>(f0, p0, NU, gb + TMP0, gb + UC0, gb + ACC0);
    csr_spmm_kernel<<<uwb, BS>>>(f1, p1, NU, gb + TMP1, gb + UC1, gb + ACC1);
    csr_spmm_kernel<<<uwb, BS>>>(f2, p2, NU, gb + TMP2, gb + UC2, gb + ACC2);
    csr_spmm_kernel<<<iwb, BS>>>(f4, p4, NI, gb + MIXED, gb + ITEMB, out + O_ITEM);
    csr_spmm_kernel<<<uwb, BS>>>(f3, p3, NU, gb + ITEMA, gb + USIMPLE, gb + ACCS);

    // ---- final ----
    attn_kernel<<<uwb, BS>>>(gb + ACC0, gb + ACC1, gb + ACC2, gb + ACCS, gb + VOFF,
                             1.0f, 0.5f, out, NU);
    gating_kernel<<<(NU + 31) / 32, gdim>>>(out, sgating_w, sgating_b, NU, 3,
                                            out + O_SG0, out + O_SG1, out + O_SG2, nullptr,
                                            nullptr, nullptr, nullptr, nullptr);
}

// round 3
// speedup vs baseline: 1.6262x; 1.0151x over previous
#include <cuda_runtime.h>
#include <cuda_fp16.h>
#include <math.h>

#define NU 100000
#define NI 50000
#define DD 64
#define EPSV 1e-12f
#define MAXH 3200000
#define MAXI 3000000

typedef long long ll;

static constexpr ll S  = (ll)NU * DD;   // 6.4M
static constexpr ll SI = (ll)NI * DD;   // 3.2M

// fp32 scratch: 4 accumulators + v vector
static constexpr ll ACC0 = 0;
static constexpr ll ACC1 = 1 * S;
static constexpr ll ACC2 = 2 * S;
static constexpr ll ACCS = 3 * S;
static constexpr ll VOFF = 4 * S;
static constexpr ll TOT32 = VOFF + 64;
__device__ float g_buf[TOT32];

// fp16 gather-format scratch
static constexpr ll XG0 = 0;          // gating outs (users)
static constexpr ll XG1 = 1 * S;
static constexpr ll XG2 = 2 * S;
static constexpr ll XGS = 3 * S;
static constexpr ll XT0 = 4 * S;      // layer-1 spmm outs
static constexpr ll XT1 = 5 * S;
static constexpr ll XT2 = 6 * S;
static constexpr ll XUS = 7 * S;
static constexpr ll XMIX = 8 * S;     // mixed (both layers)
static constexpr ll XIT  = 9 * S;     // item_emb fp16
static constexpr ll XITA = 9 * S + SI;// layer-1 new_item fp16
static constexpr ll TOT16 = 9 * S + 2 * SI;
__device__ __half g_h[TOT16];

// CSR scratch: 5 regions (hs, hj, hp, inter-by-user, inter-by-item)
static constexpr int OFFLEN = 4 * (NU + 1) + (NI + 1);
__device__ int  g_off[OFFLEN];
__device__ int  g_cur[OFFLEN];
__device__ int2 g_pair[3 * (ll)MAXH + 2 * (ll)MAXI];

// ---------------------------------------------------------------------------
__device__ __forceinline__ float warp_sum(float v) {
#pragma unroll
    for (int o = 16; o > 0; o >>= 1) v += __shfl_xor_sync(0xFFFFFFFFu, v, o);
    return v;
}

// ---------------------------------------------------------------------------
__global__ void zero_int_kernel(int* p, int n) {
    int i = blockIdx.x * blockDim.x + threadIdx.x;
    if (i < n) p[i] = 0;
}

// 4 edges per thread
__global__ void hist_kernel(const int* __restrict__ row, int nnz, int* __restrict__ cnt) {
    int i = (blockIdx.x * blockDim.x + threadIdx.x) * 4;
    if (i + 3 < nnz) {
        int4 r = *(const int4*)(row + i);
        atomicAdd(cnt + r.x, 1);
        atomicAdd(cnt + r.y, 1);
        atomicAdd(cnt + r.z, 1);
        atomicAdd(cnt + r.w, 1);
    } else {
        for (int j = i; j < nnz; ++j) atomicAdd(cnt + __ldg(row + j), 1);
    }
}

// one block per region; chunked exclusive scan (single pass of syncthreads)
__global__ void scan_kernel() {
    int region = blockIdx.x;
    int n = (region == 4) ? NI : NU;
    int base = region * (NU + 1);
    int* cnt = g_cur + base;
    int* off = g_off + base;
    const int T = 1024;
    int t = threadIdx.x;
    int chunk = (n + T - 1) / T;
    int lo = t * chunk;
    int hi = lo + chunk; if (hi > n) hi = n;
    int sum = 0;
    for (int i = lo; i < hi; ++i) sum += cnt[i];

    __shared__ int ws[32];
    int lane = t & 31, wid = t >> 5;
    int x = sum;
#pragma unroll
    for (int o = 1; o < 32; o <<= 1) {
        int y = __shfl_up_sync(0xFFFFFFFFu, x, o);
        if (lane >= o) x += y;
    }
    if (lane == 31) ws[wid] = x;
    __syncthreads();
    if (t < 32) {
        int y = ws[t];
#pragma unroll
        for (int o = 1; o < 32; o <<= 1) {
            int z = __shfl_up_sync(0xFFFFFFFFu, y, o);
            if (t >= o) y += z;
        }
        ws[t] = y;
    }
    __syncthreads();
    int pre = x - sum + ((wid > 0) ? ws[wid - 1] : 0);
    if (t == T - 1) off[n] = pre + sum;
    int run = pre;
    for (int i = lo; i < hi; ++i) {
        int v = cnt[i];
        off[i] = run;
        cnt[i] = run;
        run += v;
    }
}

// 4 edges per thread
__global__ void scatter_kernel(const int* __restrict__ row, const int* __restrict__ col,
                               const float* __restrict__ val, int nnz,
                               int* __restrict__ cur, int2* __restrict__ pair) {
    int i = (blockIdx.x * blockDim.x + threadIdx.x) * 4;
    if (i + 3 < nnz) {
        int4 r = *(const int4*)(row + i);
        int4 c = *(const int4*)(col + i);
        float4 v = *(const float4*)(val + i);
        int p0 = atomicAdd(cur + r.x, 1);
        int p1 = atomicAdd(cur + r.y, 1);
        int p2 = atomicAdd(cur + r.z, 1);
        int p3 = atomicAdd(cur + r.w, 1);
        pair[p0] = make_int2(c.x, __float_as_int(v.x));
        pair[p1] = make_int2(c.y, __float_as_int(v.y));
        pair[p2] = make_int2(c.z, __float_as_int(v.z));
        pair[p3] = make_int2(c.w, __float_as_int(v.w));
    } else {
        for (int j = i; j < nnz; ++j) {
            int pos = atomicAdd(cur + __ldg(row + j), 1);
            pair[pos] = make_int2(__ldg(col + j), __float_as_int(__ldg(val + j)));
        }
    }
}

// CSR SpMM, fp16 gathers, fused l2norm-accumulate. One warp per row.
// y16 optional (fp16 copy for subsequent gathers).
__global__ void csr_spmm_kernel(const int* __restrict__ off, const int2* __restrict__ pair,
                                int n_rows, const __half* __restrict__ x16,
                                __half* __restrict__ y16, float* __restrict__ acc) {
    int w = (int)(((ll)blockIdx.x * blockDim.x + threadIdx.x) >> 5);
    if (w >= n_rows) return;
    int lane = threadIdx.x & 31;
    int s = __ldg(off + w), e = __ldg(off + w + 1);
    float ax = 0.f, ay = 0.f;
    int i = s;
    for (; i + 3 < e; i += 4) {
        int2 q0 = __ldg(pair + i);
        int2 q1 = __ldg(pair + i + 1);
        int2 q2 = __ldg(pair + i + 2);
        int2 q3 = __ldg(pair + i + 3);
        __half2 h0 = __ldg((const __half2*)(x16 + (ll)q0.x * DD) + lane);
        __half2 h1 = __ldg((const __half2*)(x16 + (ll)q1.x * DD) + lane);
        __half2 h2 = __ldg((const __half2*)(x16 + (ll)q2.x * DD) + lane);
        __half2 h3 = __ldg((const __half2*)(x16 + (ll)q3.x * DD) + lane);
        float2 f0 = __half22float2(h0);
        float2 f1 = __half22float2(h1);
        float2 f2 = __half22float2(h2);
        float2 f3 = __half22float2(h3);
        float v0 = __int_as_float(q0.y), v1 = __int_as_float(q1.y);
        float v2 = __int_as_float(q2.y), v3 = __int_as_float(q3.y);
        ax = fmaf(v0, f0.x, ax); ay = fmaf(v0, f0.y, ay);
        ax = fmaf(v1, f1.x, ax); ay = fmaf(v1, f1.y, ay);
        ax = fmaf(v2, f2.x, ax); ay = fmaf(v2, f2.y, ay);
        ax = fmaf(v3, f3.x, ax); ay = fmaf(v3, f3.y, ay);
    }
    for (; i < e; ++i) {
        int2 q0 = __ldg(pair + i);
        __half2 h0 = __ldg((const __half2*)(x16 + (ll)q0.x * DD) + lane);
        float2 f0 = __half22float2(h0);
        float v0 = __int_as_float(q0.y);
        ax = fmaf(v0, f0.x, ax); ay = fmaf(v0, f0.y, ay);
    }
    ll base = (ll)w * DD + lane * 2;
    if (y16) ((__half2*)(y16 + (ll)w * DD))[lane] = __floats2half2_rn(ax, ay);
    float ss = warp_sum(ax * ax + ay * ay);
    float sc = 1.f / fmaxf(sqrtf(ss), EPSV);
    float2 a = *(const float2*)(acc + base);
    a.x = fmaf(ax, sc, a.x);
    a.y = fmaf(ay, sc, a.y);
    *(float2*)(acc + base) = a;
}

// v[d] = sum_j att_mat[d][j] * att_agg[j]
__global__ void compute_v_kernel(const float* __restrict__ att_mat,
                                 const float* __restrict__ att_agg) {
    int d = threadIdx.x;
    float s = 0.f;
#pragma unroll
    for (int j = 0; j < DD; ++j) s = fmaf(att_mat[d * DD + j], att_agg[j], s);
    g_buf[VOFF + d] = s;
}

__global__ void item_h_kernel(const float* __restrict__ src, __half* __restrict__ dst, int n2) {
    int i = blockIdx.x * blockDim.x + threadIdx.x;
    if (i < n2) {
        float2 v = ((const float2*)src)[i];
        ((__half2*)dst)[i] = __floats2half2_rn(v.x, v.y);
    }
}

// attention over fp16 inputs -> fp16 mixed. one warp per row.
__global__ void attn_h_kernel(const __half* __restrict__ c0p, const __half* __restrict__ c1p,
                              const __half* __restrict__ c2p, const __half* __restrict__ othp,
                              const float* __restrict__ v,
                              __half* __restrict__ out, int n_rows) {
    int w = (int)(((ll)blockIdx.x * blockDim.x + threadIdx.x) >> 5);
    if (w >= n_rows) return;
    int lane = threadIdx.x & 31;
    ll rb = (ll)w * DD;
    float2 c0 = __half22float2(((const __half2*)(c0p + rb))[lane]);
    float2 c1 = __half22float2(((const __half2*)(c1p + rb))[lane]);
    float2 c2 = __half22float2(((const __half2*)(c2p + rb))[lane]);
    float2 ot = __half22float2(((const __half2*)(othp + rb))[lane]);
    float2 vv = *(const float2*)(v + lane * 2);
    float w0 = warp_sum(c0.x * vv.x + c0.y * vv.y);
    float w1 = warp_sum(c1.x * vv.x + c1.y * vv.y);
    float w2 = warp_sum(c2.x * vv.x + c2.y * vv.y);
    float m = fmaxf(w0, fmaxf(w1, w2));
    float e0 = __expf(w0 - m), e1 = __expf(w1 - m), e2 = __expf(w2 - m);
    float inv = 1.f / (e0 + e1 + e2);
    float s0 = e0 * inv, s1 = e1 * inv, s2 = e2 * inv;
    float ox = 0.5f * (s0 * c0.x + s1 * c1.x + s2 * c2.x) + 0.5f * ot.x;
    float oy = 0.5f * (s0 * c0.y + s1 * c1.y + s2 * c2.y) + 0.5f * ot.y;
    ((__half2*)(out + rb))[lane] = __floats2half2_rn(ox, oy);
}

// final attention over fp32 accumulators -> fp32 out
__global__ void attn_f_kernel(const float* __restrict__ c0p, const float* __restrict__ c1p,
                              const float* __restrict__ c2p, const float* __restrict__ othp,
                              const float* __restrict__ v,
                              float* __restrict__ out, int n_rows) {
    int w = (int)(((ll)blockIdx.x * blockDim.x + threadIdx.x) >> 5);
    if (w >= n_rows) return;
    int lane = threadIdx.x & 31;
    ll base = (ll)w * DD + lane * 2;
    float2 c0 = *(const float2*)(c0p + base);
    float2 c1 = *(const float2*)(c1p + base);
    float2 c2 = *(const float2*)(c2p + base);
    float2 ot = *(const float2*)(othp + base);
    float2 vv = *(const float2*)(v + lane * 2);
    float w0 = warp_sum(c0.x * vv.x + c0.y * vv.y);
    float w1 = warp_sum(c1.x * vv.x + c1.y * vv.y);
    float w2 = warp_sum(c2.x * vv.x + c2.y * vv.y);
    float m = fmaxf(w0, fmaxf(w1, w2));
    float e0 = __expf(w0 - m), e1 = __expf(w1 - m), e2 = __expf(w2 - m);
    float inv = 1.f / (e0 + e1 + e2);
    float s0 = e0 * inv, s1 = e1 * inv, s2 = e2 * inv;
    float ox = (s0 * c0.x + s1 * c1.x + s2 * c2.x) + 0.5f * ot.x;
    float oy = (s0 * c0.y + s1 * c1.y + s2 * c2.y) + 0.5f * ot.y;
    *(float2*)(out + base) = make_float2(ox, oy);
}

// self-gating: out = in * sigmoid(in @ W_g + b_g); fp32 and/or fp16 outputs.
__global__ void gating_kernel(const float* __restrict__ in, const float* __restrict__ W,
                              const float* __restrict__ B, int n_rows, int n_gates,
                              float* o0, float* o1, float* o2, float* o3,
                              __half* h0, __half* h1, __half* h2, __half* h3) {
    __shared__ float sW[DD * DD];
    __shared__ float se[32 * DD];
    int tx = threadIdx.x, ty = threadIdx.y;
    int tid = ty * 64 + tx;
    int row0 = blockIdx.x * 32;
    for (int i = tid; i < 32 * DD; i += 256) {
        int r = i >> 6, c = i & 63;
        int gr = row0 + r;
        se[i] = (gr < n_rows) ? in[(ll)gr * DD + c] : 0.f;
    }
    float* outs[4] = {o0, o1, o2, o3};
    __half* houts[4] = {h0, h1, h2, h3};
    for (int g = 0; g < n_gates; ++g) {
        __syncthreads();
        for (int i = tid; i < DD * DD; i += 256) sW[i] = W[(ll)g * DD * DD + i];
        __syncthreads();
        float bg = B[g * DD + tx];
        float acc[8] = {0, 0, 0, 0, 0, 0, 0, 0};
#pragma unroll 8
        for (int d = 0; d < DD; ++d) {
            float wv = sW[d * DD + tx];
#pragma unroll
            for (int rr = 0; rr < 8; ++rr)
                acc[rr] = fmaf(se[(ty + 4 * rr) * DD + d], wv, acc[rr]);
        }
#pragma unroll
        for (int rr = 0; rr < 8; ++rr) {
            int r = ty + 4 * rr;
            int gr = row0 + r;
            if (gr < n_rows) {
                float z = acc[rr] + bg;
                float sig = 1.f / (1.f + __expf(-z));
                float ov = se[r * DD + tx] * sig;
                ll idx = (ll)gr * DD + tx;
                if (outs[g]) outs[g][idx] = ov;
                if (houts[g]) houts[g][idx] = __float2half(ov);
            }
        }
    }
}

// ---------------------------------------------------------------------------
static inline int blocks_for(ll threads, int bs) { return (int)((threads + bs - 1) / bs); }

extern "C" void kernel_launch(void* const* d_in, const int* in_sizes, int n_in,
                              void* d_out, int out_size) {
    const float* user_emb  = (const float*)d_in[0];
    const float* item_emb  = (const float*)d_in[1];
    const float* gating_w  = (const float*)d_in[2];
    const float* gating_b  = (const float*)d_in[3];
    const float* sgating_w = (const float*)d_in[4];
    const float* sgating_b = (const float*)d_in[5];
    const float* att_mat   = (const float*)d_in[6];
    const float* att_agg   = (const float*)d_in[7];
    const int*   hs_row = (const int*)d_in[8];
    const int*   hs_col = (const int*)d_in[9];
    const float* hs_val = (const float*)d_in[10];
    const int*   hj_row = (const int*)d_in[11];
    const int*   hj_col = (const int*)d_in[12];
    const float* hj_val = (const float*)d_in[13];
    const int*   hp_row = (const int*)d_in[14];
    const int*   hp_col = (const int*)d_in[15];
    const float* hp_val = (const float*)d_in[16];
    const int*   inter_row = (const int*)d_in[17];
    const int*   inter_col = (const int*)d_in[18];
    const float* inter_val = (const float*)d_in[19];

    const int NNZ_H = in_sizes[8];
    const int NNZ_I = in_sizes[17];

    float* out = (float*)d_out;
    const ll O_ITEM = S;
    const ll O_SG0 = S + SI;
    const ll O_SG1 = 2 * S + SI;
    const ll O_SG2 = 3 * S + SI;

    float*  gb; cudaGetSymbolAddress((void**)&gb, g_buf);
    __half* gh; cudaGetSymbolAddress((void**)&gh, g_h);
    int*   off; cudaGetSymbolAddress((void**)&off, g_off);
    int*   cur; cudaGetSymbolAddress((void**)&cur, g_cur);
    int2*  pr;  cudaGetSymbolAddress((void**)&pr, g_pair);

    const int BS = 256;
    const int hbH = blocks_for((NNZ_H + 3) / 4, BS);
    const int hbI = blocks_for((NNZ_I + 3) / 4, BS);
    const int uwb = blocks_for((ll)NU * 32, BS);
    const int iwb = blocks_for((ll)NI * 32, BS);
    dim3 gdim(64, 4);

    int* c0 = cur + 0 * (NU + 1); int* f0 = off + 0 * (NU + 1); int2* p0 = pr;
    int* c1 = cur + 1 * (NU + 1); int* f1 = off + 1 * (NU + 1); int2* p1 = pr + (ll)NNZ_H;
    int* c2 = cur + 2 * (NU + 1); int* f2 = off + 2 * (NU + 1); int2* p2 = pr + 2ll * NNZ_H;
    int* c3 = cur + 3 * (NU + 1); int* f3 = off + 3 * (NU + 1); int2* p3 = pr + 3ll * NNZ_H;
    int* c4 = cur + 4 * (NU + 1); int* f4 = off + 4 * (NU + 1); int2* p4 = pr + 3ll * NNZ_H + NNZ_I;

    // ---- CSR build ----
    zero_int_kernel<<<blocks_for(OFFLEN, BS), BS>>>(cur, OFFLEN);
    hist_kernel<<<hbH, BS>>>(hs_row, NNZ_H, c0);
    hist_kernel<<<hbH, BS>>>(hj_row, NNZ_H, c1);
    hist_kernel<<<hbH, BS>>>(hp_row, NNZ_H, c2);
    hist_kernel<<<hbI, BS>>>(inter_row, NNZ_I, c3);
    hist_kernel<<<hbI, BS>>>(inter_col, NNZ_I, c4);
    scan_kernel<<<5, 1024>>>();
    scatter_kernel<<<hbH, BS>>>(hs_row, hs_col, hs_val, NNZ_H, c0, p0);
    scatter_kernel<<<hbH, BS>>>(hj_row, hj_col, hj_val, NNZ_H, c1, p1);
    scatter_kernel<<<hbH, BS>>>(hp_row, hp_col, hp_val, NNZ_H, c2, p2);
    scatter_kernel<<<hbI, BS>>>(inter_row, inter_col, inter_val, NNZ_I, c3, p3);
    scatter_kernel<<<hbI, BS>>>(inter_col, inter_row, inter_val, NNZ_I, c4, p4);

    // ---- prologue ----
    compute_v_kernel<<<1, 64>>>(att_mat, att_agg);
    gating_kernel<<<(NU + 31) / 32, gdim>>>(user_emb, gating_w, gating_b, NU, 4,
                                            gb + ACC0, gb + ACC1, gb + ACC2, gb + ACCS,
                                            gh + XG0, gh + XG1, gh + XG2, gh + XGS);
    item_h_kernel<<<blocks_for(SI / 2, BS), BS>>>(item_emb, gh + XIT, (int)(SI / 2));
    cudaMemcpyAsync(out + O_ITEM, item_emb, SI * sizeof(float), cudaMemcpyDeviceToDevice, 0);

    // ---- layer 1 ----
    attn_h_kernel<<<uwb, BS>>>(gh + XG0, gh + XG1, gh + XG2, gh + XGS, gb + VOFF,
                               gh + XMIX, NU);
    csr_spmm_kernel<<<uwb, BS>>>(f0, p0, NU, gh + XG0, gh + XT0, gb + ACC0);
    csr_spmm_kernel<<<uwb, BS>>>(f1, p1, NU, gh + XG1, gh + XT1, gb + ACC1);
    csr_spmm_kernel<<<uwb, BS>>>(f2, p2, NU, gh + XG2, gh + XT2, gb + ACC2);
    csr_spmm_kernel<<<iwb, BS>>>(f4, p4, NI, gh + XMIX, gh + XITA, out + O_ITEM);
    csr_spmm_kernel<<<uwb, BS>>>(f3, p3, NU, gh + XIT, gh + XUS, gb + ACCS);

    // ---- layer 2 ----
    attn_h_kernel<<<uwb, BS>>>(gh + XT0, gh + XT1, gh + XT2, gh + XUS, gb + VOFF,
                               gh + XMIX, NU);
    csr_spmm_kernel<<<uwb, BS>>>(f0, p0, NU, gh + XT0, nullptr, gb + ACC0);
    csr_spmm_kernel<<<uwb, BS>>>(f1, p1, NU, gh + XT1, nullptr, gb + ACC1);
    csr_spmm_kernel<<<uwb, BS>>>(f2, p2, NU, gh + XT2, nullptr, gb + ACC2);
    csr_spmm_kernel<<<iwb, BS>>>(f4, p4, NI, gh + XMIX, nullptr, out + O_ITEM);
    csr_spmm_kernel<<<uwb, BS>>>(f3, p3, NU, gh + XITA, nullptr, gb + ACCS);

    // ---- final ----
    attn_f_kernel<<<uwb, BS>>>(gb + ACC0, gb + ACC1, gb + ACC2, gb + ACCS, gb + VOFF,
                               out, NU);
    gating_kernel<<<(NU + 31) / 32, gdim>>>(out, sgating_w, sgating_b, NU, 3,
                                            out + O_SG0, out + O_SG1, out + O_SG2, nullptr,
                                            nullptr, nullptr, nullptr, nullptr);
}